// round 2
// baseline (speedup 1.0000x reference)
#include <cuda_runtime.h>
#include <cuda_bf16.h>

// Problem shape (fixed): B=4, T=2048, C=1024, H=16, D=64
#define B_   4
#define T_   2048
#define C_   1024
#define H_   16
#define D_   64
#define M_   (B_ * T_)      // 8192 rows
#define C3_  (3 * C_)       // 3072

// Scratch (allocation-free rule: __device__ globals). Referenced directly from
// device code so kernel_launch contains ONLY kernel launches (maximally
// graph-capture safe).
__device__ float g_qkv[(size_t)M_ * C3_];   // 96 MB: [B*T, 3C]
__device__ float g_y[(size_t)M_ * C_];      // 32 MB: [B*T, C] attention output

// Buffer selectors for the templated GEMM (avoid host-side symbol address APIs)
#define BUF_EXT   0   // use the pointer argument
#define BUF_QKV   1   // g_qkv
#define BUF_Y     2   // g_y

__device__ __forceinline__ const float* resolve_src(int sel, const float* p) {
    if (sel == BUF_QKV) return g_qkv;
    if (sel == BUF_Y)   return g_y;
    return p;
}
__device__ __forceinline__ float* resolve_dst(int sel, float* p) {
    if (sel == BUF_QKV) return g_qkv;
    if (sel == BUF_Y)   return g_y;
    return p;
}

// ---------------------------------------------------------------------------
// SGEMM + bias: out[M,N] = A[M,K] @ W[K,N] + bias[N]
// BM=BN=128, BK=8, 256 threads, 8x8 micro-tile. Requires M%128==0, N%128==0, K%8==0.
// SRC_SEL / DST_SEL select between the external pointers and device globals.
// ---------------------------------------------------------------------------
template <int SRC_SEL, int DST_SEL>
__global__ __launch_bounds__(256) void sgemm_bias_kernel(
    const float* __restrict__ A_ext, const float* __restrict__ W,
    const float* __restrict__ bias, float* __restrict__ out_ext,
    int K, int N)
{
    const float* A  = resolve_src(SRC_SEL, A_ext);
    float*      out = resolve_dst(DST_SEL, out_ext);

    const int BM = 128, BN = 128, BK = 8;
    __shared__ float As[BK][BM];   // transposed A tile
    __shared__ float Bs[BK][BN];

    const int tid = threadIdx.x;
    const int m0 = blockIdx.y * BM;
    const int n0 = blockIdx.x * BN;
    const int tx = tid & 15;       // 0..15 -> output cols tx*8..tx*8+7
    const int ty = tid >> 4;       // 0..15 -> output rows ty*8..ty*8+7

    float acc[8][8];
#pragma unroll
    for (int i = 0; i < 8; i++)
#pragma unroll
        for (int j = 0; j < 8; j++) acc[i][j] = 0.f;

    // A loader: each thread loads one float4 per k-tile (128 rows x 8 k)
    const int arow = tid >> 1;
    const int ak   = (tid & 1) * 4;
    const float* Aptr = A + (size_t)(m0 + arow) * K + ak;
    // B loader: 8 rows x 128 cols, one float4 per thread
    const int brow = tid >> 5;
    const int bcol = (tid & 31) * 4;
    const float* Wptr = W + (size_t)brow * N + n0 + bcol;

    for (int kt = 0; kt < K; kt += BK) {
        float4 av = *(const float4*)(Aptr + kt);
        As[ak + 0][arow] = av.x;
        As[ak + 1][arow] = av.y;
        As[ak + 2][arow] = av.z;
        As[ak + 3][arow] = av.w;
        float4 bv = *(const float4*)(Wptr + (size_t)kt * N);
        *(float4*)&Bs[brow][bcol] = bv;
        __syncthreads();

#pragma unroll
        for (int k = 0; k < BK; k++) {
            float a[8], b[8];
            *(float4*)&a[0] = *(const float4*)&As[k][ty * 8];
            *(float4*)&a[4] = *(const float4*)&As[k][ty * 8 + 4];
            *(float4*)&b[0] = *(const float4*)&Bs[k][tx * 8];
            *(float4*)&b[4] = *(const float4*)&Bs[k][tx * 8 + 4];
#pragma unroll
            for (int i = 0; i < 8; i++)
#pragma unroll
                for (int j = 0; j < 8; j++)
                    acc[i][j] = fmaf(a[i], b[j], acc[i][j]);
        }
        __syncthreads();
    }

    float bf[8];
    *(float4*)&bf[0] = *(const float4*)&bias[n0 + tx * 8];
    *(float4*)&bf[4] = *(const float4*)&bias[n0 + tx * 8 + 4];
#pragma unroll
    for (int i = 0; i < 8; i++) {
        float* cp = out + (size_t)(m0 + ty * 8 + i) * N + n0 + tx * 8;
        float4 v0 = make_float4(acc[i][0] + bf[0], acc[i][1] + bf[1],
                                acc[i][2] + bf[2], acc[i][3] + bf[3]);
        float4 v1 = make_float4(acc[i][4] + bf[4], acc[i][5] + bf[5],
                                acc[i][6] + bf[6], acc[i][7] + bf[7]);
        *(float4*)cp = v0;
        *(float4*)(cp + 4) = v1;
    }
}

// ---------------------------------------------------------------------------
// Flash attention (causal), fp32. Reads g_qkv, writes g_y.
// Grid: (T/64 q-tiles, B*H). 256 threads. Q tile 64x64, K/V tiles 64x64.
// S/P kept in registers; row reductions + P broadcast via warp shuffles
// (16 lanes per row group). K smem stride 65 avoids 16-way conflicts.
// ---------------------------------------------------------------------------
__global__ __launch_bounds__(256) void attn_kernel()
{
    __shared__ float Qs[64 * 64];      // [row][d], stride 64
    __shared__ float KV[64 * 65];      // K then V tile, stride 65

    const int tid = threadIdx.x;
    const int tx = tid & 15;           // col group: cols tx*4..tx*4+3
    const int ty = tid >> 4;           // row group: rows ty*4..ty*4+3
    const int r0 = ty * 4, c0 = tx * 4;

    const int qt = blockIdx.x;         // q-tile index
    const int bh = blockIdx.y;
    const int b = bh >> 4, h = bh & 15;
    const int q0 = qt * 64;

    // loader mapping: 64 rows x 64 cols, float4 per pass
    const int lrow = tid >> 4;         // 0..15
    const int lcol = (tid & 15) * 4;   // 0..60

    const float scale = 0.125f;        // 1/sqrt(64)
    const float* base = g_qkv + (size_t)(b * T_) * C3_ + h * D_;

    // Load Q (pre-scaled)
#pragma unroll
    for (int p = 0; p < 4; p++) {
        int row = lrow + p * 16;
        float4 v = *(const float4*)(base + (size_t)(q0 + row) * C3_ + lcol);
        Qs[row * 64 + lcol + 0] = v.x * scale;
        Qs[row * 64 + lcol + 1] = v.y * scale;
        Qs[row * 64 + lcol + 2] = v.z * scale;
        Qs[row * 64 + lcol + 3] = v.w * scale;
    }

    float m_i[4], l_i[4], o[4][4];
#pragma unroll
    for (int i = 0; i < 4; i++) {
        m_i[i] = -1e30f;
        l_i[i] = 0.f;
#pragma unroll
        for (int j = 0; j < 4; j++) o[i][j] = 0.f;
    }
    __syncthreads();

    for (int kt = 0; kt <= qt; kt++) {
        const int k0 = kt * 64;
        // Load K tile: KV[kv_row][d], stride 65
#pragma unroll
        for (int p = 0; p < 4; p++) {
            int row = lrow + p * 16;
            float4 v = *(const float4*)(base + C_ + (size_t)(k0 + row) * C3_ + lcol);
            float* dst = &KV[row * 65 + lcol];
            dst[0] = v.x; dst[1] = v.y; dst[2] = v.z; dst[3] = v.w;
        }
        __syncthreads();

        // S = Q @ K^T (4x4 per thread)
        float s[4][4];
#pragma unroll
        for (int i = 0; i < 4; i++)
#pragma unroll
            for (int j = 0; j < 4; j++) s[i][j] = 0.f;
#pragma unroll
        for (int d = 0; d < 64; d++) {
            float qa[4], kb[4];
#pragma unroll
            for (int i = 0; i < 4; i++) qa[i] = Qs[(r0 + i) * 64 + d];
#pragma unroll
            for (int j = 0; j < 4; j++) kb[j] = KV[(c0 + j) * 65 + d];
#pragma unroll
            for (int i = 0; i < 4; i++)
#pragma unroll
                for (int j = 0; j < 4; j++)
                    s[i][j] = fmaf(qa[i], kb[j], s[i][j]);
        }
        if (kt == qt) {   // diagonal tile: causal mask (k0 == q0)
#pragma unroll
            for (int i = 0; i < 4; i++)
#pragma unroll
                for (int j = 0; j < 4; j++)
                    if (c0 + j > r0 + i) s[i][j] = -1e30f;
        }
        __syncthreads();  // done reading K; safe to overwrite KV with V

        // Load V tile
#pragma unroll
        for (int p = 0; p < 4; p++) {
            int row = lrow + p * 16;
            float4 v = *(const float4*)(base + 2 * C_ + (size_t)(k0 + row) * C3_ + lcol);
            float* dst = &KV[row * 65 + lcol];
            dst[0] = v.x; dst[1] = v.y; dst[2] = v.z; dst[3] = v.w;
        }

        // Online softmax in registers (row spread across 16 lanes)
#pragma unroll
        for (int i = 0; i < 4; i++) {
            float mx = fmaxf(fmaxf(s[i][0], s[i][1]), fmaxf(s[i][2], s[i][3]));
#pragma unroll
            for (int off = 8; off >= 1; off >>= 1)
                mx = fmaxf(mx, __shfl_xor_sync(0xffffffffu, mx, off));
            float mnew = fmaxf(m_i[i], mx);
            float alpha = __expf(m_i[i] - mnew);
            float psum = 0.f;
#pragma unroll
            for (int j = 0; j < 4; j++) {
                float p = __expf(s[i][j] - mnew);
                s[i][j] = p;
                psum += p;
            }
#pragma unroll
            for (int off = 8; off >= 1; off >>= 1)
                psum += __shfl_xor_sync(0xffffffffu, psum, off);
            l_i[i] = l_i[i] * alpha + psum;
            m_i[i] = mnew;
#pragma unroll
            for (int j = 0; j < 4; j++) o[i][j] *= alpha;
        }
        __syncthreads();  // V loaded

        // O += P @ V ; P broadcast via shuffle (lane k>>2 owns P[:, k])
#pragma unroll
        for (int k = 0; k < 64; k++) {
            float vb[4];
#pragma unroll
            for (int j = 0; j < 4; j++) vb[j] = KV[k * 65 + c0 + j];
            float pa[4];
#pragma unroll
            for (int i = 0; i < 4; i++)
                pa[i] = __shfl_sync(0xffffffffu, s[i][k & 3], k >> 2, 16);
#pragma unroll
            for (int i = 0; i < 4; i++)
#pragma unroll
                for (int j = 0; j < 4; j++)
                    o[i][j] = fmaf(pa[i], vb[j], o[i][j]);
        }
        __syncthreads();  // before next K load overwrites KV
    }

    // Normalize + write y in [B,T,C] layout (head h at cols h*64..h*64+63)
    float* ybase = g_y + (size_t)(b * T_) * C_ + h * D_;
#pragma unroll
    for (int i = 0; i < 4; i++) {
        float inv = 1.f / l_i[i];
        float4 v = make_float4(o[i][0] * inv, o[i][1] * inv,
                               o[i][2] * inv, o[i][3] * inv);
        *(float4*)(ybase + (size_t)(q0 + r0 + i) * C_ + c0) = v;
    }
}

// ---------------------------------------------------------------------------
extern "C" void kernel_launch(void* const* d_in, const int* in_sizes, int n_in,
                              void* d_out, int out_size)
{
    const float* x      = (const float*)d_in[0];
    const float* W_attn = (const float*)d_in[1];
    const float* b_attn = (const float*)d_in[2];
    const float* W_proj = (const float*)d_in[3];
    const float* b_proj = (const float*)d_in[4];
    float* out = (float*)d_out;

    // 1) QKV GEMM: [8192,1024] @ [1024,3072] + bias -> g_qkv
    sgemm_bias_kernel<BUF_EXT, BUF_QKV><<<dim3(C3_ / 128, M_ / 128), 256>>>(
        x, W_attn, b_attn, nullptr, C_, C3_);
    // 2) Causal flash attention: g_qkv -> g_y
    attn_kernel<<<dim3(T_ / 64, B_ * H_), 256>>>();
    // 3) Output projection: [8192,1024] @ [1024,1024] + bias -> out
    sgemm_bias_kernel<BUF_Y, BUF_EXT><<<dim3(C_ / 128, M_ / 128), 256>>>(
        nullptr, W_proj, b_proj, out, C_, C_);
}

// round 4
// speedup vs baseline: 1.6303x; 1.6303x over previous
#include <cuda_runtime.h>
#include <cuda_bf16.h>
#include <cstdint>

// Problem shape (fixed): B=4, T=2048, C=1024, H=16, D=64
#define B_   4
#define T_   2048
#define C_   1024
#define H_   16
#define D_   64
#define M_   (B_ * T_)      // 8192 rows
#define C3_  (3 * C_)       // 3072

// Scratch (allocation-free rule: __device__ globals)
__device__ float g_qkv[(size_t)M_ * C3_];   // 96 MB: [B*T, 3C]
__device__ float g_y[(size_t)M_ * C_];      // 32 MB: [B*T, C]

#define BUF_EXT   0
#define BUF_QKV   1
#define BUF_Y     2

__device__ __forceinline__ const float* resolve_src(int sel, const float* p) {
    if (sel == BUF_QKV) return g_qkv;
    if (sel == BUF_Y)   return g_y;
    return p;
}
__device__ __forceinline__ float* resolve_dst(int sel, float* p) {
    if (sel == BUF_QKV) return g_qkv;
    if (sel == BUF_Y)   return g_y;
    return p;
}

__device__ __forceinline__ void cp_async16(void* smem_dst, const void* gmem_src) {
    uint32_t s = (uint32_t)__cvta_generic_to_shared(smem_dst);
    asm volatile("cp.async.cg.shared.global [%0], [%1], 16;\n" :: "r"(s), "l"(gmem_src));
}
__device__ __forceinline__ void cp_async_commit() {
    asm volatile("cp.async.commit_group;\n");
}
__device__ __forceinline__ void cp_async_wait_all() {
    asm volatile("cp.async.wait_group 0;\n");
}
__device__ __forceinline__ uint32_t f2tf32(float x) {
    uint32_t u;
    asm("cvt.rna.tf32.f32 %0, %1;\n" : "=r"(u) : "f"(x));
    return u;
}

// ---------------------------------------------------------------------------
// TF32 tensor-core GEMM + bias: out[M,N] = A[M,K] @ W[K,N] + bias[N]
// CTA tile 128x128x16, 256 threads (8 warps, 2x4), warp tile 64x32.
// mma.sync m16n8k8 tf32, cp.async double-buffered smem.
// Requires M%128==0, N%128==0, K%16==0.
// ---------------------------------------------------------------------------
#define BM 128
#define BN 128
#define BKT 16
#define A_STRIDE 20    // BKT + 4 pad: fragment loads hit all 32 banks
#define B_STRIDE 136   // BN + 8 pad:  fragment loads hit all 32 banks

template <int SRC_SEL, int DST_SEL>
__global__ __launch_bounds__(256) void gemm_tf32_kernel(
    const float* __restrict__ A_ext, const float* __restrict__ W,
    const float* __restrict__ bias, float* __restrict__ out_ext,
    int K, int N)
{
    const float* A  = resolve_src(SRC_SEL, A_ext);
    float*      out = resolve_dst(DST_SEL, out_ext);

    __shared__ float As[2][BM][A_STRIDE];
    __shared__ float Bs[2][BKT][B_STRIDE];

    const int tid  = threadIdx.x;
    const int warp = tid >> 5;
    const int lane = tid & 31;
    const int gid  = lane >> 2;   // 0..7
    const int tq   = lane & 3;    // 0..3

    const int warp_m = warp & 1;  // 0..1 -> rows warp_m*64
    const int warp_n = warp >> 1; // 0..3 -> cols warp_n*32

    const int m0 = blockIdx.y * BM;
    const int n0 = blockIdx.x * BN;

    // Loader mappings (16B chunks)
    // A tile: 128 rows x 16 floats = 512 chunks; thread does chunks tid, tid+256
    const int a_row0 = tid >> 2;            // chunk c=tid   -> row c/4
    const int a_kc0  = (tid & 3) * 4;
    // B tile: 16 rows x 128 floats = 512 chunks
    const int b_row0 = tid >> 5;            // c/32
    const int b_col0 = (tid & 31) * 4;

    float acc[4][4][4];
#pragma unroll
    for (int i = 0; i < 4; i++)
#pragma unroll
        for (int j = 0; j < 4; j++)
#pragma unroll
            for (int r = 0; r < 4; r++) acc[i][j][r] = 0.f;

    const int NT = K / BKT;

    auto load_tile = [&](int kt, int buf) {
        // A chunks
#pragma unroll
        for (int i = 0; i < 2; i++) {
            int row = a_row0 + i * 64;     // (tid + i*256)/4
            int kc  = a_kc0;
            cp_async16(&As[buf][row][kc],
                       A + (size_t)(m0 + row) * K + kt * BKT + kc);
        }
        // B chunks
#pragma unroll
        for (int i = 0; i < 2; i++) {
            int row = b_row0 + i * 8;      // (tid + i*256)/32
            int col = b_col0;
            cp_async16(&Bs[buf][row][col],
                       W + (size_t)(kt * BKT + row) * N + n0 + col);
        }
        cp_async_commit();
    };

    int buf = 0;
    load_tile(0, 0);

    for (int kt = 0; kt < NT; kt++) {
        cp_async_wait_all();
        __syncthreads();

        if (kt + 1 < NT) load_tile(kt + 1, buf ^ 1);

        // Compute on buf: 2 k-steps of m16n8k8
#pragma unroll
        for (int ks = 0; ks < BKT; ks += 8) {
            uint32_t af[4][4], bf[4][2];
#pragma unroll
            for (int mf = 0; mf < 4; mf++) {
                int mrow = warp_m * 64 + mf * 16;
                af[mf][0] = f2tf32(As[buf][mrow + gid    ][ks + tq    ]);
                af[mf][1] = f2tf32(As[buf][mrow + gid + 8][ks + tq    ]);
                af[mf][2] = f2tf32(As[buf][mrow + gid    ][ks + tq + 4]);
                af[mf][3] = f2tf32(As[buf][mrow + gid + 8][ks + tq + 4]);
            }
#pragma unroll
            for (int nf = 0; nf < 4; nf++) {
                int ncol = warp_n * 32 + nf * 8;
                bf[nf][0] = f2tf32(Bs[buf][ks + tq    ][ncol + gid]);
                bf[nf][1] = f2tf32(Bs[buf][ks + tq + 4][ncol + gid]);
            }
#pragma unroll
            for (int mf = 0; mf < 4; mf++)
#pragma unroll
                for (int nf = 0; nf < 4; nf++) {
                    asm volatile(
                        "mma.sync.aligned.m16n8k8.row.col.f32.tf32.tf32.f32 "
                        "{%0,%1,%2,%3}, {%4,%5,%6,%7}, {%8,%9}, {%0,%1,%2,%3};\n"
                        : "+f"(acc[mf][nf][0]), "+f"(acc[mf][nf][1]),
                          "+f"(acc[mf][nf][2]), "+f"(acc[mf][nf][3])
                        : "r"(af[mf][0]), "r"(af[mf][1]),
                          "r"(af[mf][2]), "r"(af[mf][3]),
                          "r"(bf[nf][0]), "r"(bf[nf][1]));
                }
        }
        buf ^= 1;
    }

    // Epilogue: bias + store.
    // C frag: c0=C[gid][2tq], c1=C[gid][2tq+1], c2=C[gid+8][2tq], c3=C[gid+8][2tq+1]
#pragma unroll
    for (int nf = 0; nf < 4; nf++) {
        int colp = n0 + warp_n * 32 + nf * 8 + 2 * tq;
        float2 bb = *(const float2*)&bias[colp];
#pragma unroll
        for (int mf = 0; mf < 4; mf++) {
            int row0 = m0 + warp_m * 64 + mf * 16 + gid;
            float2 v0 = make_float2(acc[mf][nf][0] + bb.x, acc[mf][nf][1] + bb.y);
            float2 v1 = make_float2(acc[mf][nf][2] + bb.x, acc[mf][nf][3] + bb.y);
            *(float2*)(out + (size_t)row0 * N + colp)       = v0;
            *(float2*)(out + (size_t)(row0 + 8) * N + colp) = v1;
        }
    }
}

// ---------------------------------------------------------------------------
// Flash attention (causal), fp32. Reads g_qkv, writes g_y. (Unchanged.)
// ---------------------------------------------------------------------------
__global__ __launch_bounds__(256) void attn_kernel()
{
    __shared__ float Qs[64 * 64];
    __shared__ float KV[64 * 65];

    const int tid = threadIdx.x;
    const int tx = tid & 15;
    const int ty = tid >> 4;
    const int r0 = ty * 4, c0 = tx * 4;

    const int qt = blockIdx.x;
    const int bh = blockIdx.y;
    const int b = bh >> 4, h = bh & 15;
    const int q0 = qt * 64;

    const int lrow = tid >> 4;
    const int lcol = (tid & 15) * 4;

    const float scale = 0.125f;
    const float* base = g_qkv + (size_t)(b * T_) * C3_ + h * D_;

#pragma unroll
    for (int p = 0; p < 4; p++) {
        int row = lrow + p * 16;
        float4 v = *(const float4*)(base + (size_t)(q0 + row) * C3_ + lcol);
        Qs[row * 64 + lcol + 0] = v.x * scale;
        Qs[row * 64 + lcol + 1] = v.y * scale;
        Qs[row * 64 + lcol + 2] = v.z * scale;
        Qs[row * 64 + lcol + 3] = v.w * scale;
    }

    float m_i[4], l_i[4], o[4][4];
#pragma unroll
    for (int i = 0; i < 4; i++) {
        m_i[i] = -1e30f;
        l_i[i] = 0.f;
#pragma unroll
        for (int j = 0; j < 4; j++) o[i][j] = 0.f;
    }
    __syncthreads();

    for (int kt = 0; kt <= qt; kt++) {
        const int k0 = kt * 64;
#pragma unroll
        for (int p = 0; p < 4; p++) {
            int row = lrow + p * 16;
            float4 v = *(const float4*)(base + C_ + (size_t)(k0 + row) * C3_ + lcol);
            float* dst = &KV[row * 65 + lcol];
            dst[0] = v.x; dst[1] = v.y; dst[2] = v.z; dst[3] = v.w;
        }
        __syncthreads();

        float s[4][4];
#pragma unroll
        for (int i = 0; i < 4; i++)
#pragma unroll
            for (int j = 0; j < 4; j++) s[i][j] = 0.f;
#pragma unroll
        for (int d = 0; d < 64; d++) {
            float qa[4], kb[4];
#pragma unroll
            for (int i = 0; i < 4; i++) qa[i] = Qs[(r0 + i) * 64 + d];
#pragma unroll
            for (int j = 0; j < 4; j++) kb[j] = KV[(c0 + j) * 65 + d];
#pragma unroll
            for (int i = 0; i < 4; i++)
#pragma unroll
                for (int j = 0; j < 4; j++)
                    s[i][j] = fmaf(qa[i], kb[j], s[i][j]);
        }
        if (kt == qt) {
#pragma unroll
            for (int i = 0; i < 4; i++)
#pragma unroll
                for (int j = 0; j < 4; j++)
                    if (c0 + j > r0 + i) s[i][j] = -1e30f;
        }
        __syncthreads();

#pragma unroll
        for (int p = 0; p < 4; p++) {
            int row = lrow + p * 16;
            float4 v = *(const float4*)(base + 2 * C_ + (size_t)(k0 + row) * C3_ + lcol);
            float* dst = &KV[row * 65 + lcol];
            dst[0] = v.x; dst[1] = v.y; dst[2] = v.z; dst[3] = v.w;
        }

#pragma unroll
        for (int i = 0; i < 4; i++) {
            float mx = fmaxf(fmaxf(s[i][0], s[i][1]), fmaxf(s[i][2], s[i][3]));
#pragma unroll
            for (int off = 8; off >= 1; off >>= 1)
                mx = fmaxf(mx, __shfl_xor_sync(0xffffffffu, mx, off));
            float mnew = fmaxf(m_i[i], mx);
            float alpha = __expf(m_i[i] - mnew);
            float psum = 0.f;
#pragma unroll
            for (int j = 0; j < 4; j++) {
                float p = __expf(s[i][j] - mnew);
                s[i][j] = p;
                psum += p;
            }
#pragma unroll
            for (int off = 8; off >= 1; off >>= 1)
                psum += __shfl_xor_sync(0xffffffffu, psum, off);
            l_i[i] = l_i[i] * alpha + psum;
            m_i[i] = mnew;
#pragma unroll
            for (int j = 0; j < 4; j++) o[i][j] *= alpha;
        }
        __syncthreads();

#pragma unroll
        for (int k = 0; k < 64; k++) {
            float vb[4];
#pragma unroll
            for (int j = 0; j < 4; j++) vb[j] = KV[k * 65 + c0 + j];
            float pa[4];
#pragma unroll
            for (int i = 0; i < 4; i++)
                pa[i] = __shfl_sync(0xffffffffu, s[i][k & 3], k >> 2, 16);
#pragma unroll
            for (int i = 0; i < 4; i++)
#pragma unroll
                for (int j = 0; j < 4; j++)
                    o[i][j] = fmaf(pa[i], vb[j], o[i][j]);
        }
        __syncthreads();
    }

    float* ybase = g_y + (size_t)(b * T_) * C_ + h * D_;
#pragma unroll
    for (int i = 0; i < 4; i++) {
        float inv = 1.f / l_i[i];
        float4 v = make_float4(o[i][0] * inv, o[i][1] * inv,
                               o[i][2] * inv, o[i][3] * inv);
        *(float4*)(ybase + (size_t)(q0 + r0 + i) * C_ + c0) = v;
    }
}

// ---------------------------------------------------------------------------
extern "C" void kernel_launch(void* const* d_in, const int* in_sizes, int n_in,
                              void* d_out, int out_size)
{
    const float* x      = (const float*)d_in[0];
    const float* W_attn = (const float*)d_in[1];
    const float* b_attn = (const float*)d_in[2];
    const float* W_proj = (const float*)d_in[3];
    const float* b_proj = (const float*)d_in[4];
    float* out = (float*)d_out;

    // 1) QKV GEMM (tf32 tensor cores): [8192,1024] @ [1024,3072] + bias -> g_qkv
    gemm_tf32_kernel<BUF_EXT, BUF_QKV><<<dim3(C3_ / BN, M_ / BM), 256>>>(
        x, W_attn, b_attn, nullptr, C_, C3_);
    // 2) Causal flash attention: g_qkv -> g_y
    attn_kernel<<<dim3(T_ / 64, B_ * H_), 256>>>();
    // 3) Output projection (tf32): [8192,1024] @ [1024,1024] + bias -> out
    gemm_tf32_kernel<BUF_Y, BUF_EXT><<<dim3(C_ / BN, M_ / BM), 256>>>(
        nullptr, W_proj, b_proj, out, C_, C_);
}

// round 5
// speedup vs baseline: 3.1342x; 1.9224x over previous
#include <cuda_runtime.h>
#include <cuda_bf16.h>
#include <cstdint>

// Problem shape (fixed): B=4, T=2048, C=1024, H=16, D=64
#define B_   4
#define T_   2048
#define C_   1024
#define H_   16
#define D_   64
#define M_   (B_ * T_)      // 8192 rows
#define C3_  (3 * C_)       // 3072

// Scratch (allocation-free rule: __device__ globals)
__device__ float g_qkv[(size_t)M_ * C3_];   // 96 MB: [B*T, 3C]
__device__ float g_y[(size_t)M_ * C_];      // 32 MB: [B*T, C]

#define BUF_EXT   0
#define BUF_QKV   1
#define BUF_Y     2

__device__ __forceinline__ const float* resolve_src(int sel, const float* p) {
    if (sel == BUF_QKV) return g_qkv;
    if (sel == BUF_Y)   return g_y;
    return p;
}
__device__ __forceinline__ float* resolve_dst(int sel, float* p) {
    if (sel == BUF_QKV) return g_qkv;
    if (sel == BUF_Y)   return g_y;
    return p;
}

__device__ __forceinline__ void cp_async16(void* smem_dst, const void* gmem_src) {
    uint32_t s = (uint32_t)__cvta_generic_to_shared(smem_dst);
    asm volatile("cp.async.cg.shared.global [%0], [%1], 16;\n" :: "r"(s), "l"(gmem_src));
}
__device__ __forceinline__ void cp_async_commit() {
    asm volatile("cp.async.commit_group;\n");
}
__device__ __forceinline__ void cp_async_wait_all() {
    asm volatile("cp.async.wait_group 0;\n");
}
__device__ __forceinline__ uint32_t f2tf32(float x) {
    uint32_t u;
    asm("cvt.rna.tf32.f32 %0, %1;\n" : "=r"(u) : "f"(x));
    return u;
}
__device__ __forceinline__ void mma_tf32(float* c, const uint32_t* a,
                                         uint32_t b0, uint32_t b1) {
    asm volatile(
        "mma.sync.aligned.m16n8k8.row.col.f32.tf32.tf32.f32 "
        "{%0,%1,%2,%3}, {%4,%5,%6,%7}, {%8,%9}, {%0,%1,%2,%3};\n"
        : "+f"(c[0]), "+f"(c[1]), "+f"(c[2]), "+f"(c[3])
        : "r"(a[0]), "r"(a[1]), "r"(a[2]), "r"(a[3]), "r"(b0), "r"(b1));
}

// ---------------------------------------------------------------------------
// TF32 tensor-core GEMM + bias (unchanged from round 4)
// ---------------------------------------------------------------------------
#define BM 128
#define BN 128
#define BKT 16
#define A_STRIDE 20
#define B_STRIDE 136

template <int SRC_SEL, int DST_SEL>
__global__ __launch_bounds__(256) void gemm_tf32_kernel(
    const float* __restrict__ A_ext, const float* __restrict__ W,
    const float* __restrict__ bias, float* __restrict__ out_ext,
    int K, int N)
{
    const float* A  = resolve_src(SRC_SEL, A_ext);
    float*      out = resolve_dst(DST_SEL, out_ext);

    __shared__ float As[2][BM][A_STRIDE];
    __shared__ float Bs[2][BKT][B_STRIDE];

    const int tid  = threadIdx.x;
    const int warp = tid >> 5;
    const int lane = tid & 31;
    const int gid  = lane >> 2;
    const int tq   = lane & 3;

    const int warp_m = warp & 1;
    const int warp_n = warp >> 1;

    const int m0 = blockIdx.y * BM;
    const int n0 = blockIdx.x * BN;

    const int a_row0 = tid >> 2;
    const int a_kc0  = (tid & 3) * 4;
    const int b_row0 = tid >> 5;
    const int b_col0 = (tid & 31) * 4;

    float acc[4][4][4];
#pragma unroll
    for (int i = 0; i < 4; i++)
#pragma unroll
        for (int j = 0; j < 4; j++)
#pragma unroll
            for (int r = 0; r < 4; r++) acc[i][j][r] = 0.f;

    const int NT = K / BKT;

    auto load_tile = [&](int kt, int buf) {
#pragma unroll
        for (int i = 0; i < 2; i++) {
            int row = a_row0 + i * 64;
            cp_async16(&As[buf][row][a_kc0],
                       A + (size_t)(m0 + row) * K + kt * BKT + a_kc0);
        }
#pragma unroll
        for (int i = 0; i < 2; i++) {
            int row = b_row0 + i * 8;
            cp_async16(&Bs[buf][row][b_col0],
                       W + (size_t)(kt * BKT + row) * N + n0 + b_col0);
        }
        cp_async_commit();
    };

    int buf = 0;
    load_tile(0, 0);

    for (int kt = 0; kt < NT; kt++) {
        cp_async_wait_all();
        __syncthreads();

        if (kt + 1 < NT) load_tile(kt + 1, buf ^ 1);

#pragma unroll
        for (int ks = 0; ks < BKT; ks += 8) {
            uint32_t af[4][4], bf[4][2];
#pragma unroll
            for (int mf = 0; mf < 4; mf++) {
                int mrow = warp_m * 64 + mf * 16;
                af[mf][0] = f2tf32(As[buf][mrow + gid    ][ks + tq    ]);
                af[mf][1] = f2tf32(As[buf][mrow + gid + 8][ks + tq    ]);
                af[mf][2] = f2tf32(As[buf][mrow + gid    ][ks + tq + 4]);
                af[mf][3] = f2tf32(As[buf][mrow + gid + 8][ks + tq + 4]);
            }
#pragma unroll
            for (int nf = 0; nf < 4; nf++) {
                int ncol = warp_n * 32 + nf * 8;
                bf[nf][0] = f2tf32(Bs[buf][ks + tq    ][ncol + gid]);
                bf[nf][1] = f2tf32(Bs[buf][ks + tq + 4][ncol + gid]);
            }
#pragma unroll
            for (int mf = 0; mf < 4; mf++)
#pragma unroll
                for (int nf = 0; nf < 4; nf++)
                    mma_tf32(acc[mf][nf], af[mf], bf[nf][0], bf[nf][1]);
        }
        buf ^= 1;
    }

#pragma unroll
    for (int nf = 0; nf < 4; nf++) {
        int colp = n0 + warp_n * 32 + nf * 8 + 2 * tq;
        float2 bb = *(const float2*)&bias[colp];
#pragma unroll
        for (int mf = 0; mf < 4; mf++) {
            int row0 = m0 + warp_m * 64 + mf * 16 + gid;
            float2 v0 = make_float2(acc[mf][nf][0] + bb.x, acc[mf][nf][1] + bb.y);
            float2 v1 = make_float2(acc[mf][nf][2] + bb.x, acc[mf][nf][3] + bb.y);
            *(float2*)(out + (size_t)row0 * N + colp)       = v0;
            *(float2*)(out + (size_t)(row0 + 8) * N + colp) = v1;
        }
    }
}

// ---------------------------------------------------------------------------
// Tensor-core flash attention (causal), tf32 mma. Reads g_qkv, writes g_y.
// 128 threads = 4 warps; Q tile 64x64; warp w owns q-rows w*16..w*16+15.
// K buffer is reused for P (K dead after S-mma). Smem 2x 64x68 u32 = 34.8KB.
// ---------------------------------------------------------------------------
#define AS_ 68   // padded stride: fragment LDS conflict-free

__global__ __launch_bounds__(128) void attn_tc_kernel()
{
    __shared__ uint32_t KPs[64][AS_];   // K tile (tf32 bits), then P tile
    __shared__ uint32_t Vs[64][AS_];    // V tile (tf32 bits)

    const int tid  = threadIdx.x;
    const int warp = tid >> 5;
    const int lane = tid & 31;
    const int gid  = lane >> 2;   // 0..7
    const int tq   = lane & 3;    // 0..3

    const int qt = gridDim.x - 1 - blockIdx.x;   // longest tiles first
    const int bh = blockIdx.y;
    const int b = bh >> 4, h = bh & 15;
    const int q0 = qt * 64;
    const int qrow = warp * 16;

    const int lrow = tid >> 4;         // 0..7
    const int lcol = (tid & 15) * 4;   // 0..60

    const float scale = 0.125f;
    const float* base = g_qkv + (size_t)(b * T_) * C3_ + h * D_;

    // ---- Stage Q (scaled) into KPs, then build tf32 A-fragments in regs ----
#pragma unroll
    for (int p = 0; p < 8; p++) {
        int row = lrow + p * 8;
        float4 v = *(const float4*)(base + (size_t)(q0 + row) * C3_ + lcol);
        KPs[row][lcol + 0] = __float_as_uint(v.x * scale);
        KPs[row][lcol + 1] = __float_as_uint(v.y * scale);
        KPs[row][lcol + 2] = __float_as_uint(v.z * scale);
        KPs[row][lcol + 3] = __float_as_uint(v.w * scale);
    }
    __syncthreads();

    uint32_t qa[8][4];
#pragma unroll
    for (int ch = 0; ch < 8; ch++) {
        qa[ch][0] = f2tf32(__uint_as_float(KPs[qrow + gid    ][ch * 8 + tq    ]));
        qa[ch][1] = f2tf32(__uint_as_float(KPs[qrow + gid + 8][ch * 8 + tq    ]));
        qa[ch][2] = f2tf32(__uint_as_float(KPs[qrow + gid    ][ch * 8 + tq + 4]));
        qa[ch][3] = f2tf32(__uint_as_float(KPs[qrow + gid + 8][ch * 8 + tq + 4]));
    }
    __syncthreads();

    float m_i[2] = {-1e30f, -1e30f};
    float l_i[2] = {0.f, 0.f};
    float o[8][4];
#pragma unroll
    for (int nf = 0; nf < 8; nf++)
#pragma unroll
        for (int r = 0; r < 4; r++) o[nf][r] = 0.f;

    for (int kt = 0; kt <= qt; kt++) {
        const int k0 = kt * 64;
        // ---- Load K and V tiles, converting to tf32 bits at store ----
#pragma unroll
        for (int p = 0; p < 8; p++) {
            int row = lrow + p * 8;
            float4 kv = *(const float4*)(base + C_ + (size_t)(k0 + row) * C3_ + lcol);
            KPs[row][lcol + 0] = f2tf32(kv.x);
            KPs[row][lcol + 1] = f2tf32(kv.y);
            KPs[row][lcol + 2] = f2tf32(kv.z);
            KPs[row][lcol + 3] = f2tf32(kv.w);
            float4 vv = *(const float4*)(base + 2 * C_ + (size_t)(k0 + row) * C3_ + lcol);
            Vs[row][lcol + 0] = f2tf32(vv.x);
            Vs[row][lcol + 1] = f2tf32(vv.y);
            Vs[row][lcol + 2] = f2tf32(vv.z);
            Vs[row][lcol + 3] = f2tf32(vv.w);
        }
        __syncthreads();

        // ---- S = Q @ K^T : warp computes rows qrow..qrow+15, cols 0..63 ----
        float s[8][4];
#pragma unroll
        for (int nf = 0; nf < 8; nf++)
#pragma unroll
            for (int r = 0; r < 4; r++) s[nf][r] = 0.f;

#pragma unroll
        for (int ch = 0; ch < 8; ch++) {
            uint32_t bf0[8], bf1[8];
#pragma unroll
            for (int nf = 0; nf < 8; nf++) {
                bf0[nf] = KPs[nf * 8 + gid][ch * 8 + tq    ];
                bf1[nf] = KPs[nf * 8 + gid][ch * 8 + tq + 4];
            }
#pragma unroll
            for (int nf = 0; nf < 8; nf++)
                mma_tf32(s[nf], qa[ch], bf0[nf], bf1[nf]);
        }

        // ---- Causal mask on diagonal tile (k0 == q0) ----
        if (kt == qt) {
#pragma unroll
            for (int nf = 0; nf < 8; nf++) {
                int col = nf * 8 + 2 * tq;
                int row0 = qrow + gid, row1 = qrow + gid + 8;
                if (col     > row0) s[nf][0] = -1e30f;
                if (col + 1 > row0) s[nf][1] = -1e30f;
                if (col     > row1) s[nf][2] = -1e30f;
                if (col + 1 > row1) s[nf][3] = -1e30f;
            }
        }

        // ---- Online softmax (rows r=0: regs 0,1 ; r=1: regs 2,3) ----
#pragma unroll
        for (int r = 0; r < 2; r++) {
            float mx = -1e30f;
#pragma unroll
            for (int nf = 0; nf < 8; nf++)
                mx = fmaxf(mx, fmaxf(s[nf][2 * r], s[nf][2 * r + 1]));
            mx = fmaxf(mx, __shfl_xor_sync(0xffffffffu, mx, 1));
            mx = fmaxf(mx, __shfl_xor_sync(0xffffffffu, mx, 2));
            float mnew = fmaxf(m_i[r], mx);
            float alpha = __expf(m_i[r] - mnew);
            float psum = 0.f;
#pragma unroll
            for (int nf = 0; nf < 8; nf++) {
                float p0 = __expf(s[nf][2 * r]     - mnew);
                float p1 = __expf(s[nf][2 * r + 1] - mnew);
                s[nf][2 * r]     = p0;
                s[nf][2 * r + 1] = p1;
                psum += p0 + p1;
            }
            psum += __shfl_xor_sync(0xffffffffu, psum, 1);
            psum += __shfl_xor_sync(0xffffffffu, psum, 2);
            l_i[r] = l_i[r] * alpha + psum;
            m_i[r] = mnew;
#pragma unroll
            for (int nf = 0; nf < 8; nf++) {
                o[nf][2 * r]     *= alpha;
                o[nf][2 * r + 1] *= alpha;
            }
        }

        // ---- Write P (tf32 bits) into K buffer; all warps must be done with K ----
        __syncthreads();
#pragma unroll
        for (int nf = 0; nf < 8; nf++) {
            int col = nf * 8 + 2 * tq;
            KPs[qrow + gid    ][col    ] = f2tf32(s[nf][0]);
            KPs[qrow + gid    ][col + 1] = f2tf32(s[nf][1]);
            KPs[qrow + gid + 8][col    ] = f2tf32(s[nf][2]);
            KPs[qrow + gid + 8][col + 1] = f2tf32(s[nf][3]);
        }
        __syncwarp();   // warp reads back only its own 16 rows

        // ---- O += P @ V ----
#pragma unroll
        for (int ch = 0; ch < 8; ch++) {
            uint32_t pa[4];
            pa[0] = KPs[qrow + gid    ][ch * 8 + tq    ];
            pa[1] = KPs[qrow + gid + 8][ch * 8 + tq    ];
            pa[2] = KPs[qrow + gid    ][ch * 8 + tq + 4];
            pa[3] = KPs[qrow + gid + 8][ch * 8 + tq + 4];
            uint32_t vb0[8], vb1[8];
#pragma unroll
            for (int nf = 0; nf < 8; nf++) {
                vb0[nf] = Vs[ch * 8 + tq    ][nf * 8 + gid];
                vb1[nf] = Vs[ch * 8 + tq + 4][nf * 8 + gid];
            }
#pragma unroll
            for (int nf = 0; nf < 8; nf++)
                mma_tf32(o[nf], pa, vb0[nf], vb1[nf]);
        }
        __syncthreads();   // before next K/V load overwrites KPs/Vs
    }

    // ---- Normalize + write y [B,T,C], head h at cols h*64.. ----
#pragma unroll
    for (int r = 0; r < 2; r++) {
        float inv = 1.f / l_i[r];
        int row = q0 + qrow + gid + 8 * r;
        float* yb = g_y + (size_t)(b * T_ + row) * C_ + h * D_;
#pragma unroll
        for (int nf = 0; nf < 8; nf++) {
            float2 v = make_float2(o[nf][2 * r] * inv, o[nf][2 * r + 1] * inv);
            *(float2*)(yb + nf * 8 + 2 * tq) = v;
        }
    }
}

// ---------------------------------------------------------------------------
extern "C" void kernel_launch(void* const* d_in, const int* in_sizes, int n_in,
                              void* d_out, int out_size)
{
    const float* x      = (const float*)d_in[0];
    const float* W_attn = (const float*)d_in[1];
    const float* b_attn = (const float*)d_in[2];
    const float* W_proj = (const float*)d_in[3];
    const float* b_proj = (const float*)d_in[4];
    float* out = (float*)d_out;

    // 1) QKV GEMM (tf32): [8192,1024] @ [1024,3072] + bias -> g_qkv
    gemm_tf32_kernel<BUF_EXT, BUF_QKV><<<dim3(C3_ / BN, M_ / BM), 256>>>(
        x, W_attn, b_attn, nullptr, C_, C3_);
    // 2) Causal flash attention (tf32 tensor cores): g_qkv -> g_y
    attn_tc_kernel<<<dim3(T_ / 64, B_ * H_), 128>>>();
    // 3) Output projection (tf32): [8192,1024] @ [1024,1024] + bias -> out
    gemm_tf32_kernel<BUF_Y, BUF_EXT><<<dim3(C_ / BN, M_ / BM), 256>>>(
        nullptr, W_proj, b_proj, out, C_, C_);
}